// round 17
// baseline (speedup 1.0000x reference)
#include <cuda_runtime.h>
#include <cuda_fp16.h>
#include <cstdint>

#define NN 50000
#define EE 800000
#define GG 64
#define FF 64
#define BN_EPS 1e-5f

// ---------------- scratch (static device globals; zero-initialized at load) --
// Invariant: d_cnt_in, d_ssum, d_fsum, d_fsq, d_pooled, d_cnt are ZERO at entry
// of every kernel_launch call (static init covers call 1; k_fc tail re-zeros).
__device__ __half d_h[(size_t)NN * FF];    // GEMM output (fp16) / gather source
__device__ float  d_y[(size_t)NN * FF];    // gather output / GEMM input (fp32)
__device__ float  d_s[NN];                 // layer-1 scalar aggregate
__device__ float  d_dinv[NN];              // per-node deg^-1/2 (precomputed)
__device__ int    d_cnt_in[NN];            // in-degree counters (zeroed in tail)
__device__ int    d_ptr[NN + 1];           // CSR row pointers (by dst)
__device__ int    d_rank[EE];              // per-edge rank within dst row
__device__ int2   d_csr[EE + NN];          // {src, bitcast(norm)}; self incl.
__device__ float  d_ssum[2];               // scalar sum / sumsq (layer 1)
__device__ float  d_fsum[3][FF];           // per-feature sums, layers 2..4
__device__ float  d_fsq[3][FF];
__device__ float  d_pooled[GG * FF];
__device__ float  d_cnt[GG];

// ---------------- PDL helpers -------------------------------------------------
__device__ __forceinline__ void grid_dep_wait() {
    asm volatile("griddepcontrol.wait;" ::: "memory");
}

// ---------------- setup ------------------------------------------------------
__global__ void k_count(const int* __restrict__ ei, int E_) {
    int e = blockIdx.x * blockDim.x + threadIdx.x;
    if (e < E_) d_rank[e] = atomicAdd(&d_cnt_in[ei[E_ + e]], 1);
}

__global__ void k_scan() {
    __shared__ int sums[1024];
    int t = threadIdx.x;
    grid_dep_wait();
    const int CH = (NN + 1023) / 1024;   // 49
    int start = t * CH;
    int end = start + CH; if (end > NN) end = NN;
    int s = 0;
    for (int i = start; i < end; i++) s += d_cnt_in[i] + 1;   // +1 self-loop
    sums[t] = s;
    __syncthreads();
    for (int off = 1; off < 1024; off <<= 1) {
        int v = (t >= off) ? sums[t - off] : 0;
        __syncthreads();
        sums[t] += v;
        __syncthreads();
    }
    int excl = (t == 0) ? 0 : sums[t - 1];
    for (int i = start; i < end; i++) {
        d_ptr[i] = excl;
        excl += d_cnt_in[i] + 1;
    }
    if (t == 1023) d_ptr[NN] = excl;
}

__global__ void k_dinvself(const float* __restrict__ x) {
    int n = blockIdx.x * blockDim.x + threadIdx.x;
    float xv = (n < NN) ? __ldg(&x[n]) : 0.f;
    grid_dep_wait();
    if (n >= NN) return;
    float di = rsqrtf((float)(d_cnt_in[n] + 1));
    float d2 = di * di;
    d_dinv[n] = di;
    d_csr[d_ptr[n]] = make_int2(n, __float_as_int(d2));
    d_s[n] = xv * d2;
}

__global__ void k_fill(const int* __restrict__ ei, const float* __restrict__ x, int E_) {
    int e = blockIdx.x * blockDim.x + threadIdx.x;
    int r = 0, c = 0; float xr = 0.f;
    if (e < E_) {
        r = __ldg(&ei[e]); c = __ldg(&ei[E_ + e]);
        xr = __ldg(&x[r]);
    }
    grid_dep_wait();
    if (e >= E_) return;
    float nm = d_dinv[r] * d_dinv[c];
    int p = d_ptr[c] + 1 + d_rank[e];
    d_csr[p] = make_int2(r, __float_as_int(nm));
    atomicAdd(&d_s[c], xr * nm);
}

// ---------------- layer-1 stats ----------------------------------------------
__global__ void k_stats_s() {
    grid_dep_wait();
    float s = 0.f, q = 0.f;
    for (int n = blockIdx.x * blockDim.x + threadIdx.x; n < NN; n += gridDim.x * blockDim.x) {
        float v = d_s[n];
        s += v; q = fmaf(v, v, q);
    }
    for (int o = 16; o; o >>= 1) {
        s += __shfl_down_sync(0xffffffffu, s, o);
        q += __shfl_down_sync(0xffffffffu, q, o);
    }
    __shared__ float sh[2][8];
    int w = threadIdx.x >> 5;
    if ((threadIdx.x & 31) == 0) { sh[0][w] = s; sh[1][w] = q; }
    __syncthreads();
    if (threadIdx.x == 0) {
        s = 0.f; q = 0.f;
        for (int i = 0; i < 8; i++) { s += sh[0][i]; q += sh[1][i]; }
        atomicAdd(&d_ssum[0], s);
        atomicAdd(&d_ssum[1], q);
    }
}

// ---------------- GEMM: 128-row tile, fp16 Z in smem, 8x4 micro-tile --------
template <bool FROM_S>
__global__ void __launch_bounds__(256) k_gemm(int L, const float* __restrict__ W,
                       const float* __restrict__ Wp,
                       const float* __restrict__ g, const float* __restrict__ bt) {
    __shared__ __align__(16) __half Zh[FF][144];
    __shared__ __align__(16) float  Ws[FF][FF];
    __shared__ float sa[FF], sc[FF];
    int t = threadIdx.x;
    int base = blockIdx.x * 128;

    {   // input-only prologue
        const float4* W4 = (const float4*)W;
        float4* Ws4 = (float4*)&Ws[0][0];
        #pragma unroll
        for (int i = 0; i < 4; i++) Ws4[t + i * 256] = W4[t + i * 256];
    }
    float w1v = 0.f, gv = 0.f, btv = 0.f;
    if (t < FF) {
        gv = __ldg(&g[t]); btv = __ldg(&bt[t]);
        if (FROM_S) w1v = __ldg(&Wp[t]);
    }

    grid_dep_wait();

    if (t < FF) {
        float inv_n = 1.0f / (float)NN;
        if (FROM_S) {
            float ms = d_ssum[0] * inv_n;
            float vs = d_ssum[1] * inv_n - ms * ms;
            float ia = gv * rsqrtf(vs * w1v * w1v + BN_EPS);
            float A = ia * w1v;
            sa[t] = A;
            sc[t] = btv - A * ms;
        } else {
            float m = d_fsum[L][t] * inv_n;
            float v = d_fsq[L][t] * inv_n - m * m;
            float ia = gv * rsqrtf(v + BN_EPS);
            sa[t] = ia;
            sc[t] = btv - ia * m;
        }
    }
    __syncthreads();

    {
        int lr = t >> 1;
        int row = base + lr;
        int c0 = (t & 1) * 32;
        if (FROM_S) {
            float sval = (row < NN) ? d_s[row] : 0.f;
            #pragma unroll
            for (int i = 0; i < 32; i++) {
                int cc = c0 + i;
                Zh[cc][lr] = __float2half(fmaxf(sa[cc] * sval + sc[cc], 0.f));
            }
        } else if (row < NN) {
            #pragma unroll
            for (int i = 0; i < 8; i++) {
                int cc = c0 + i * 4;
                float4 v = *(const float4*)(d_y + (size_t)row * FF + cc);
                Zh[cc + 0][lr] = __float2half(fmaxf(sa[cc + 0] * v.x + sc[cc + 0], 0.f));
                Zh[cc + 1][lr] = __float2half(fmaxf(sa[cc + 1] * v.y + sc[cc + 1], 0.f));
                Zh[cc + 2][lr] = __float2half(fmaxf(sa[cc + 2] * v.z + sc[cc + 2], 0.f));
                Zh[cc + 3][lr] = __float2half(fmaxf(sa[cc + 3] * v.w + sc[cc + 3], 0.f));
            }
        } else {
            #pragma unroll
            for (int i = 0; i < 32; i++) Zh[c0 + i][lr] = __float2half(0.f);
        }
    }
    __syncthreads();

    int tx = t & 15, ty = t >> 4;
    float acc[8][4] = {};
    #pragma unroll 8
    for (int k = 0; k < FF; k++) {
        uint4 zu = *(const uint4*)&Zh[k][ty * 8];
        float4 wv = *(const float4*)&Ws[k][tx * 4];
        const __half2* zh = (const __half2*)&zu;
        float2 z0 = __half22float2(zh[0]);
        float2 z1 = __half22float2(zh[1]);
        float2 z2 = __half22float2(zh[2]);
        float2 z3 = __half22float2(zh[3]);
        float zr[8] = {z0.x, z0.y, z1.x, z1.y, z2.x, z2.y, z3.x, z3.y};
        float wc[4] = {wv.x, wv.y, wv.z, wv.w};
        #pragma unroll
        for (int r = 0; r < 8; r++)
            #pragma unroll
            for (int j = 0; j < 4; j++)
                acc[r][j] = fmaf(zr[r], wc[j], acc[r][j]);
    }
    __syncthreads();

    __half* zbuf = &Zh[0][0];
    #pragma unroll
    for (int r = 0; r < 8; r++) {
        int sr = ty * 8 + r;
        *(__half2*)&zbuf[sr * 72 + tx * 4]     = __floats2half2_rn(acc[r][0], acc[r][1]);
        *(__half2*)&zbuf[sr * 72 + tx * 4 + 2] = __floats2half2_rn(acc[r][2], acc[r][3]);
    }
    __syncthreads();

    {
        int lr = t >> 1;
        int row = base + lr;
        if (row < NN) {
            int seg = (t & 1) * 32;
            const uint4* src = (const uint4*)&zbuf[lr * 72 + seg];
            uint4* dst = (uint4*)(d_h + (size_t)row * FF + seg);
            #pragma unroll
            for (int i = 0; i < 4; i++) dst[i] = src[i];
        }
    }
}

// ---------------- 64-wide gather: 8 lanes/node, uint4/lane, 8-deep unroll ----
// Lane fl = lane&7 owns halves [8fl, 8fl+8); sub = lane>>3 picks one of 4
// concurrent nodes per warp. 8-deep first stage -> 32 independent h-lines
// in flight per warp; then 4-deep, then scalar tail.
__global__ void k_gather64(int L) {
    __shared__ float smS[8][64];
    __shared__ float smQ[8][64];
    int t = threadIdx.x;
    int lane = t & 31, w = t >> 5;          // 8 warps / block
    int fl = lane & 7, sub = lane >> 3;     // 4 nodes / warp
    grid_dep_wait();
    float rS[8] = {}, rQ[8] = {};
    const uint4* hb = (const uint4*)d_h;    // 8 uint4 (16B) per 64-half row

    for (int n = (blockIdx.x * 8 + w) * 4 + sub; n < NN; n += gridDim.x * 32) {
        int p = d_ptr[n], en = d_ptr[n + 1];
        float acc[8] = {};
        // ---- 8-deep stage
        for (; p + 7 < en; p += 8) {
            int2 v[8]; uint4 u[8];
            #pragma unroll
            for (int j = 0; j < 8; j++) v[j] = __ldg(&d_csr[p + j]);
            #pragma unroll
            for (int j = 0; j < 8; j++) u[j] = __ldg(hb + (size_t)v[j].x * 8 + fl);
            #pragma unroll
            for (int j = 0; j < 8; j++) {
                float m = __int_as_float(v[j].y);
                const __half2* h = (const __half2*)&u[j];
                #pragma unroll
                for (int i = 0; i < 4; i++) {
                    float2 f = __half22float2(h[i]);
                    acc[2*i]   = fmaf(f.x, m, acc[2*i]);
                    acc[2*i+1] = fmaf(f.y, m, acc[2*i+1]);
                }
            }
        }
        // ---- 4-deep stage
        for (; p + 3 < en; p += 4) {
            int2 v[4]; uint4 u[4];
            #pragma unroll
            for (int j = 0; j < 4; j++) v[j] = __ldg(&d_csr[p + j]);
            #pragma unroll
            for (int j = 0; j < 4; j++) u[j] = __ldg(hb + (size_t)v[j].x * 8 + fl);
            #pragma unroll
            for (int j = 0; j < 4; j++) {
                float m = __int_as_float(v[j].y);
                const __half2* h = (const __half2*)&u[j];
                #pragma unroll
                for (int i = 0; i < 4; i++) {
                    float2 f = __half22float2(h[i]);
                    acc[2*i]   = fmaf(f.x, m, acc[2*i]);
                    acc[2*i+1] = fmaf(f.y, m, acc[2*i+1]);
                }
            }
        }
        // ---- scalar tail
        for (; p < en; p++) {
            int2 v0 = __ldg(&d_csr[p]);
            uint4 u0 = __ldg(hb + (size_t)v0.x * 8 + fl);
            float m0 = __int_as_float(v0.y);
            const __half2* h0 = (const __half2*)&u0;
            #pragma unroll
            for (int i = 0; i < 4; i++) {
                float2 f0 = __half22float2(h0[i]);
                acc[2*i]   = fmaf(f0.x, m0, acc[2*i]);
                acc[2*i+1] = fmaf(f0.y, m0, acc[2*i+1]);
            }
        }
        float4* yrow = (float4*)(d_y + (size_t)n * FF + 8 * fl);
        yrow[0] = make_float4(acc[0], acc[1], acc[2], acc[3]);
        yrow[1] = make_float4(acc[4], acc[5], acc[6], acc[7]);
        #pragma unroll
        for (int i = 0; i < 8; i++) {
            rS[i] += acc[i];
            rQ[i] = fmaf(acc[i], acc[i], rQ[i]);
        }
    }
    #pragma unroll
    for (int i = 0; i < 8; i++) {
        rS[i] += __shfl_down_sync(0xffffffffu, rS[i], 16);
        rS[i] += __shfl_down_sync(0xffffffffu, rS[i], 8);
        rQ[i] += __shfl_down_sync(0xffffffffu, rQ[i], 16);
        rQ[i] += __shfl_down_sync(0xffffffffu, rQ[i], 8);
    }
    if (lane < 8) {
        #pragma unroll
        for (int i = 0; i < 8; i++) {
            smS[w][8 * fl + i] = rS[i];
            smQ[w][8 * fl + i] = rQ[i];
        }
    }
    __syncthreads();
    if (t < 64) {
        float s = 0.f, q = 0.f;
        #pragma unroll
        for (int i = 0; i < 8; i++) { s += smS[i][t]; q += smQ[i][t]; }
        atomicAdd(&d_fsum[L][t], s);
        atomicAdd(&d_fsq[L][t], q);
    }
}

// ---------------- pooling (BN4+ReLU inline) ----------------------------------
__global__ void k_pool(const int* __restrict__ batch,
                       const float* __restrict__ g4, const float* __restrict__ bt4) {
    int t = threadIdx.x;
    int f = t & 63, rg = t >> 6;
    int base = blockIdx.x * 256;
    float gv = __ldg(&g4[f]), btv = __ldg(&bt4[f]);
    grid_dep_wait();
    float inv_n = 1.0f / (float)NN;
    float m = d_fsum[2][f] * inv_n;
    float v = d_fsq[2][f] * inv_n - m * m;
    float ia = gv * rsqrtf(v + BN_EPS);
    float af = ia, cf = btv - ia * m;
    float acc = 0.f, cacc = 0.f;
    int gcur = -1;
    for (int i = 0; i < 64; i++) {
        int n = base + rg + 4 * i;
        if (n >= NN) break;
        int g = batch[n];
        if (g != gcur) {
            if (gcur >= 0) {
                atomicAdd(&d_pooled[gcur * FF + f], acc);
                if (f == 0) atomicAdd(&d_cnt[gcur], cacc);
            }
            gcur = g; acc = 0.f; cacc = 0.f;
        }
        float vv = fmaxf(af * d_y[(size_t)n * FF + f] + cf, 0.f);
        acc += vv; cacc += 1.f;
    }
    if (gcur >= 0) {
        atomicAdd(&d_pooled[gcur * FF + f], acc);
        if (f == 0) atomicAdd(&d_cnt[gcur], cacc);
    }
}

// ---------------- MLP head ----------------------------------------------------
__global__ void k_fc(const float* __restrict__ fw1, const float* __restrict__ fb1,
                     const float* __restrict__ fw2, const float* __restrict__ fb2,
                     float* __restrict__ out) {
    __shared__ float FWt[FF][129];
    __shared__ float P[FF];
    __shared__ float H[128];
    int t = threadIdx.x;               // 128 threads
    int g = blockIdx.x;                // 64 blocks

    for (int idx = t; idx < 128 * FF; idx += 128) {
        int j = idx >> 6, f = idx & 63;
        FWt[f][j] = fw1[idx];
    }
    grid_dep_wait();

    if (t < FF) {
        float cc = d_cnt[g]; cc = (cc < 1.f) ? 1.f : cc;
        P[t] = d_pooled[g * FF + t] / cc;
    }
    __syncthreads();

    {
        float s = fb1[t];
        #pragma unroll 16
        for (int f = 0; f < FF; f++) s = fmaf(P[f], FWt[f][t], s);
        H[t] = fmaxf(s, 0.f);
    }
    __syncthreads();

    if (t < 10) {
        float s = fb2[t];
        #pragma unroll 16
        for (int j = 0; j < 128; j++) s = fmaf(H[j], fw2[t * 128 + j], s);
        out[g * 10 + t] = s;
    }

    // ---- tail-zero for next call
    if (t < FF) d_pooled[g * FF + t] = 0.f;
    if (t == 0) d_cnt[g] = 0.f;
    for (int i = g * 128 + t; i < NN; i += GG * 128) d_cnt_in[i] = 0;
    if (g == 0) {
        if (t < 2) d_ssum[t] = 0.f;
        if (t < 128) {
            ((float*)d_fsum)[t] = 0.f; ((float*)d_fsum)[t + 64] = 0.f;
            ((float*)d_fsq)[t]  = 0.f; ((float*)d_fsq)[t + 64]  = 0.f;
        }
        if (t < 64) { ((float*)d_fsum)[128 + t] = 0.f; ((float*)d_fsq)[128 + t] = 0.f; }
    }
}

// ---------------- launch -----------------------------------------------------
extern "C" void kernel_launch(void* const* d_in, const int* in_sizes, int n_in,
                              void* d_out, int out_size) {
    const float* x   = (const float*)d_in[0];
    const int*   ei  = (const int*)d_in[1];
    const int*   bat = (const int*)d_in[2];
    const float* W1  = (const float*)d_in[3];
    const float* g1  = (const float*)d_in[5];
    const float* bt1 = (const float*)d_in[6];
    const float* W2  = (const float*)d_in[7];
    const float* g2  = (const float*)d_in[9];
    const float* bt2 = (const float*)d_in[10];
    const float* W3  = (const float*)d_in[11];
    const float* g3  = (const float*)d_in[13];
    const float* bt3 = (const float*)d_in[14];
    const float* W4  = (const float*)d_in[15];
    const float* g4  = (const float*)d_in[17];
    const float* bt4 = (const float*)d_in[18];
    const float* fw1 = (const float*)d_in[19];
    const float* fb1 = (const float*)d_in[20];
    const float* fw2 = (const float*)d_in[21];
    const float* fb2 = (const float*)d_in[22];
    float* out = (float*)d_out;

    int E_ = in_sizes[1] / 2;
    if (E_ > EE) E_ = EE;

    const int TB = 256;
    int nb_n = (NN + TB - 1) / TB;
    int nb_e = (E_ + TB - 1) / TB;
    int nb_g = (NN + 127) / 128;
    const int GATHER_BLKS = 592;

    cudaLaunchAttribute pdl_attr;
    pdl_attr.id = cudaLaunchAttributeProgrammaticStreamSerialization;
    pdl_attr.val.programmaticStreamSerializationAllowed = 1;
    cudaLaunchConfig_t cfg = {};
    cfg.blockDim = dim3(TB, 1, 1);
    cfg.dynamicSmemBytes = 0;
    cfg.stream = 0;
    cfg.attrs = &pdl_attr;
    cfg.numAttrs = 1;

    k_count<<<nb_e, TB>>>(ei, E_);

    cfg.gridDim = dim3(1, 1, 1); cfg.blockDim = dim3(1024, 1, 1);
    cudaLaunchKernelEx(&cfg, k_scan);

    cfg.blockDim = dim3(TB, 1, 1);
    cfg.gridDim = dim3(nb_n, 1, 1);
    cudaLaunchKernelEx(&cfg, k_dinvself, x);

    cfg.gridDim = dim3(nb_e, 1, 1);
    cudaLaunchKernelEx(&cfg, k_fill, ei, x, E_);

    cfg.gridDim = dim3(128, 1, 1);
    cudaLaunchKernelEx(&cfg, k_stats_s);

    // layer 2
    cfg.gridDim = dim3(nb_g, 1, 1);
    cudaLaunchKernelEx(&cfg, k_gemm<true>, 0, W2, W1, g1, bt1);
    cfg.gridDim = dim3(GATHER_BLKS, 1, 1);
    cudaLaunchKernelEx(&cfg, k_gather64, 0);

    // layer 3
    cfg.gridDim = dim3(nb_g, 1, 1);
    cudaLaunchKernelEx(&cfg, k_gemm<false>, 0, W3, (const float*)nullptr, g2, bt2);
    cfg.gridDim = dim3(GATHER_BLKS, 1, 1);
    cudaLaunchKernelEx(&cfg, k_gather64, 1);

    // layer 4
    cfg.gridDim = dim3(nb_g, 1, 1);
    cudaLaunchKernelEx(&cfg, k_gemm<false>, 1, W4, (const float*)nullptr, g3, bt3);
    cfg.gridDim = dim3(GATHER_BLKS, 1, 1);
    cudaLaunchKernelEx(&cfg, k_gather64, 2);

    // pool + head (+ tail-zero)
    cfg.gridDim = dim3((NN + 255) / 256, 1, 1);
    cudaLaunchKernelEx(&cfg, k_pool, bat, g4, bt4);

    cfg.gridDim = dim3(GG, 1, 1); cfg.blockDim = dim3(128, 1, 1);
    cudaLaunchKernelEx(&cfg, k_fc, fw1, fb1, fw2, fb2, out);
}